// round 13
// baseline (speedup 1.0000x reference)
#include <cuda_runtime.h>
#include <cuda_bf16.h>
#include <cuda_fp16.h>
#include <math.h>
#include <stdint.h>

// ---------------- problem constants ----------------
#define MM   32
#define NN   16
#define BB   256
#define TT   8
#define HQ   1024
#define HS   256
#define D_Q_IN   160
#define D_SIG_IN 1184
#define D_S_IN   416
#define D_FC2_IN 1280
#define D_FC2_H  2560

// ---------------- device scratch ----------------
__device__ __half g_WqihH [4 * HQ * D_Q_IN];
__device__ __half g_WqhhH [4 * HQ * HQ];
__device__ __half g_WsigihH[4 * HQ * D_SIG_IN];
__device__ __half g_WsighhH[4 * HQ * HQ];
__device__ __half g_WsihH [4 * HS * D_S_IN];
__device__ __half g_WshhH [4 * HS * HS];
__device__ __half g_fc1H  [HS * HQ];
__device__ __half g_fc2aH [D_FC2_H * D_FC2_IN];
__device__ __half g_fc2bH [NN * MM * D_FC2_H];
__device__ __half g_hQh  [2][BB * HQ];
__device__ __half g_hSigh[2][BB * HQ];
__device__ __half g_hSh  [2][BB * HS];
__device__ __half g_out5h[BB * D_Q_IN];
__device__ __half g_out6h[BB * D_Q_IN];
__device__ __half g_out7h[BB * D_Q_IN];
__device__ __half g_out1h[BB * HS];
__device__ __half g_a2h  [BB * D_FC2_H];
__device__ float g_cQ  [BB * HQ];
__device__ float g_cSig[BB * HQ];
__device__ float g_cS  [BB * HS];
__device__ float g_xprior[2][BB * MM];
__device__ float g_dy   [BB * NN];
__device__ float g_yprev0[BB * NN];

__device__ __forceinline__ float sigmoidf(float x) { return 1.f / (1.f + expf(-x)); }
__device__ __forceinline__ void gdc_wait() {
    asm volatile("griddepcontrol.wait;" ::: "memory");
}

// ---------------- merged weight f32->f16 conversion (one launch) ----------------
struct CvtJobs {
    const float* src[9];
    __half* dst[9];
    int K[9];
    int H[9];       // 0 = identity row map, else gate interleave with hidden H
    int row0[10];
};

__global__ void cvt_all(CvtJobs J)
{
    gdc_wait();
    int b = blockIdx.x;
    int j = 0;
    #pragma unroll
    for (int i = 1; i < 9; i++) if (b >= J.row0[i]) j = i;
    int rp = b - J.row0[j];
    int K = J.K[j], H = J.H[j];
    int ro = H ? ((rp & 3) * H + (rp >> 2)) : rp;
    const float4* s = (const float4*)(J.src[j] + (size_t)ro * K);
    __half2* d = (__half2*)(J.dst[j] + (size_t)rp * K);
    for (int k = threadIdx.x; k < (K >> 2); k += blockDim.x) {
        float4 v = s[k];
        d[2 * k]     = __floats2half2_rn(v.x, v.y);
        d[2 * k + 1] = __floats2half2_rn(v.z, v.w);
    }
}

// ---------------- init: zero states, y_prev0 = tanh(x0[:, :16]) ----------------
__global__ void init_kernel(const float* __restrict__ x0, float* __restrict__ yprev0)
{
    gdc_wait();
    int idx = blockIdx.x * blockDim.x + threadIdx.x;
    __half hz = __float2half(0.f);
    if (idx < BB * HQ) {
        g_hQh[0][idx] = hz; g_hQh[1][idx] = hz; g_cQ[idx] = 0.f;
        g_hSigh[0][idx] = hz; g_hSigh[1][idx] = hz; g_cSig[idx] = 0.f;
    }
    if (idx < BB * HS) { g_hSh[0][idx] = hz; g_hSh[1][idx] = hz; g_cS[idx] = 0.f; }
    if (idx < BB * NN) {
        int b = idx / NN, n = idx % NN;
        yprev0[idx] = tanhf(x0[b * MM + n]);
    }
}

// ---------------- fused prologue + fc5/6/7 (fp16 outputs) ----------------
__global__ void pre_fc_kernel(const float* __restrict__ x_post,
                              const float* __restrict__ x_post_prev,
                              const float* __restrict__ x_prior_prev,
                              const float* __restrict__ y_t,
                              const float* __restrict__ y_prev,
                              float* __restrict__ x_prior,
                              float* __restrict__ dy_buf,
                              const float* __restrict__ w5, const float* __restrict__ b5,
                              const float* __restrict__ w6, const float* __restrict__ b6,
                              const float* __restrict__ w7, const float* __restrict__ b7,
                              __half* __restrict__ out5,
                              __half* __restrict__ out6,
                              __half* __restrict__ out7)
{
    gdc_wait();   // predecessor (fc2b) writes x_post we read below
    int b = blockIdx.x;
    int tid = threadIdx.x;
    __shared__ float fwu[32], fwe[32], obs[32];

    if (tid < 32) {
        int lane = tid;
        float xp   = x_post[b * MM + lane];
        float xpp  = x_post_prev[b * MM + lane];
        float xprp = x_prior_prev[b * MM + lane];

        float xpr = xp + 0.1f * sinf(xp);
        x_prior[b * MM + lane] = xpr;

        float de = xp - xpp;
        float du = xp - xprp;
        float se = de * de, su = du * du;
        #pragma unroll
        for (int o = 16; o > 0; o >>= 1) {
            se += __shfl_xor_sync(0xffffffffu, se, o);
            su += __shfl_xor_sync(0xffffffffu, su, o);
        }
        fwe[lane] = de / fmaxf(sqrtf(se), 1e-12f);
        fwu[lane] = du / fmaxf(sqrtf(su), 1e-12f);

        float y     = (lane < NN) ? y_t[b * NN + lane]    : 0.f;
        float ypv   = (lane < NN) ? y_prev[b * NN + lane] : 0.f;
        float ypred = (lane < NN) ? tanhf(xpr)            : 0.f;
        float d1 = y - ypv;
        float d2 = y - ypred;
        if (lane < NN) dy_buf[b * NN + lane] = d2;
        float s1 = d1 * d1, s2 = d2 * d2;
        #pragma unroll
        for (int o = 16; o > 0; o >>= 1) {
            s1 += __shfl_xor_sync(0xffffffffu, s1, o);
            s2 += __shfl_xor_sync(0xffffffffu, s2, o);
        }
        if (lane < NN) {
            obs[lane]      = d1 / fmaxf(sqrtf(s1), 1e-12f);
            obs[NN + lane] = d2 / fmaxf(sqrtf(s2), 1e-12f);
        }
    }
    __syncthreads();

    for (int o = tid; o < 480; o += 192) {
        int which = o / 160, oo = o - which * 160;
        const float* W; const float* Bv; const float* xs; __half* O;
        if (which == 0)      { W = w5; Bv = b5; xs = fwu; O = out5; }
        else if (which == 1) { W = w6; Bv = b6; xs = fwe; O = out6; }
        else                 { W = w7; Bv = b7; xs = obs; O = out7; }
        float acc = Bv[oo];
        const float* wr = W + oo * 32;
        #pragma unroll
        for (int k = 0; k < 32; k++) acc += xs[k] * wr[k];
        O[b * 160 + oo] = __float2half(fmaxf(acc, 0.f));
    }
}

// ---------------- FP16-storage tensor-core multi-segment GEMM ----------------
// BM=64 BN=64 BK=32, 128 threads (2x2 warps, warp 32x32), 4-stage cp.async,
// one __syncthreads/iter, ldmatrix loads.
// PDL: weight (B) tiles for stages 0..2 prefetch BEFORE griddepcontrol.wait —
// weights are written only at graph head, never by the immediate predecessor.
// Activation (A) loads happen after the wait.
struct GSeg {
    const __half* X;   // [BB, K] fp16 activations
    const __half* W;   // fp16 weights, row stride ldw (may carry column offset)
    int K;
    int ldw;
};

#define LDAH 40
#define NSTAGE 4

__device__ __forceinline__ void cpa16(void* s, const void* g) {
    uint32_t sa = (uint32_t)__cvta_generic_to_shared(s);
    asm volatile("cp.async.cg.shared.global [%0], [%1], 16;\n" :: "r"(sa), "l"(g));
}
__device__ __forceinline__ void ldm_x4(uint32_t* r, const __half* p) {
    uint32_t a = (uint32_t)__cvta_generic_to_shared(p);
    asm volatile("ldmatrix.sync.aligned.m8n8.x4.shared.b16 {%0,%1,%2,%3}, [%4];"
                 : "=r"(r[0]), "=r"(r[1]), "=r"(r[2]), "=r"(r[3]) : "r"(a));
}

__global__ void __launch_bounds__(128) gemm_tc(
    GSeg s0, GSeg s1, GSeg s2, int nseg,
    const float* __restrict__ bias0, const float* __restrict__ bias1,
    __half* __restrict__ Zh, int Nout, int act,
    int lstmH, float* __restrict__ cst, __half* __restrict__ hH,
    const float* __restrict__ dyp, const float* __restrict__ xpr,
    float* __restrict__ outp)
{
    __shared__ __half As[NSTAGE][64 * LDAH];
    __shared__ __half Bs[NSTAGE][64 * LDAH];

    int tid  = threadIdx.x;
    int lane = tid & 31;
    int wid  = tid >> 5;
    int wm   = wid & 1;
    int wn   = wid >> 1;
    int gid  = lane >> 2;
    int tg   = lane & 3;

    int row0 = blockIdx.y * 64;
    int col0 = blockIdx.x * 64;

    int srow = tid >> 2;          // 0..31
    int scol = (tid & 3) * 8;     // 0,8,16,24

    int lt   = lane >> 3;
    int lrow = lane & 7;
    int aRowOff = ((lt & 1) * 8 + lrow);
    int aKOff   = (lt >> 1) * 8;
    int bRowOff = ((lt >> 1) * 8 + lrow);
    int bKOff   = (lt & 1) * 8;

    int totK = s0.K + ((nseg > 1) ? s1.K : 0) + ((nseg > 2) ? s2.K : 0);
    int niter = totK >> 5;

    float c[2][4][4];
    #pragma unroll
    for (int mt = 0; mt < 2; mt++)
        #pragma unroll
        for (int nt = 0; nt < 4; nt++)
            #pragma unroll
            for (int r = 0; r < 4; r++) c[mt][nt][r] = 0.f;

    auto issueB = [&](int it, int p) {
        int kb = it << 5;
        const __half* W = s0.W; int ldw = s0.ldw;
        if (kb >= s0.K) {
            kb -= s0.K;
            if (nseg > 2 && kb >= s1.K) { kb -= s1.K; W = s2.W; ldw = s2.ldw; }
            else                        {             W = s1.W; ldw = s1.ldw; }
        }
        #pragma unroll
        for (int i = 0; i < 2; i++) {
            int r = srow + 32 * i;
            cpa16(&Bs[p][r * LDAH + scol], W + (size_t)(col0 + r) * ldw + kb + scol);
        }
    };
    auto issueA = [&](int it, int p) {
        int kb = it << 5;
        const __half* X = s0.X; int K = s0.K;
        if (kb >= s0.K) {
            kb -= s0.K;
            if (nseg > 2 && kb >= s1.K) { kb -= s1.K; X = s2.X; K = s2.K; }
            else                        {             X = s1.X; K = s1.K; }
        }
        #pragma unroll
        for (int i = 0; i < 2; i++) {
            int r = srow + 32 * i;
            cpa16(&As[p][r * LDAH + scol], X + (size_t)(row0 + r) * K + kb + scol);
        }
    };
    auto issue = [&](int it, int p) { issueA(it, p); issueB(it, p); };

    // pre-wait: weight prefetch for stages 0..2 (safe vs immediate predecessor)
    #pragma unroll
    for (int i = 0; i < NSTAGE - 1; i++)
        if (i < niter) issueB(i, i);

    gdc_wait();   // predecessor's activation writes now visible

    // post-wait: activation loads; commits form groups g0={B0,B1,B2,A0}, g1={A1}, g2={A2}
    #pragma unroll
    for (int i = 0; i < NSTAGE - 1; i++) {
        if (i < niter) issueA(i, i);
        asm volatile("cp.async.commit_group;\n" ::);
    }

    for (int it = 0; it < niter; it++) {
        int p = it & (NSTAGE - 1);
        asm volatile("cp.async.wait_group %0;\n" :: "n"(NSTAGE - 2));
        __syncthreads();
        if (it + NSTAGE - 1 < niter) issue(it + NSTAGE - 1, (it + NSTAGE - 1) & (NSTAGE - 1));
        asm volatile("cp.async.commit_group;\n" ::);

        #pragma unroll
        for (int ks = 0; ks < 2; ks++) {
            int kk = ks * 16;
            uint32_t af[2][4];
            #pragma unroll
            for (int mt = 0; mt < 2; mt++) {
                int r = wm * 32 + mt * 16 + aRowOff;
                ldm_x4(af[mt], &As[p][r * LDAH + kk + aKOff]);
            }
            uint32_t bf[4][2];
            #pragma unroll
            for (int ntp = 0; ntp < 2; ntp++) {
                int n = wn * 32 + ntp * 16 + bRowOff;
                uint32_t tmp[4];
                ldm_x4(tmp, &Bs[p][n * LDAH + kk + bKOff]);
                bf[2 * ntp][0]     = tmp[0];
                bf[2 * ntp][1]     = tmp[1];
                bf[2 * ntp + 1][0] = tmp[2];
                bf[2 * ntp + 1][1] = tmp[3];
            }
            #pragma unroll
            for (int mt = 0; mt < 2; mt++)
                #pragma unroll
                for (int nt = 0; nt < 4; nt++) {
                    asm volatile(
                        "mma.sync.aligned.m16n8k16.row.col.f32.f16.f16.f32 "
                        "{%0,%1,%2,%3}, {%4,%5,%6,%7}, {%8,%9}, {%0,%1,%2,%3};\n"
                        : "+f"(c[mt][nt][0]), "+f"(c[mt][nt][1]),
                          "+f"(c[mt][nt][2]), "+f"(c[mt][nt][3])
                        : "r"(af[mt][0]), "r"(af[mt][1]), "r"(af[mt][2]), "r"(af[mt][3]),
                          "r"(bf[nt][0]), "r"(bf[nt][1]));
                }
        }
    }

    if (lstmH > 0) {
        const int H = lstmH;
        #pragma unroll
        for (int mt = 0; mt < 2; mt++) {
            int r = row0 + wm * 32 + mt * 16 + gid;
            #pragma unroll
            for (int nt = 0; nt < 4; nt++) {
                int cb = col0 + wn * 32 + nt * 8 + tg * 2;
                int ro0 = (cb & 3) * H + (cb >> 2);
                int ro1 = ((cb + 1) & 3) * H + ((cb + 1) >> 2);
                float b0a = bias0[ro0] + bias1[ro0];
                float b0b = bias0[ro1] + bias1[ro1];
                float z0 = c[mt][nt][0] + b0a;
                float z1 = c[mt][nt][1] + b0b;
                float z2 = c[mt][nt][2] + b0a;
                float z3 = c[mt][nt][3] + b0b;
                float p0 = __shfl_xor_sync(0xffffffffu, z0, 1);
                float p1 = __shfl_xor_sync(0xffffffffu, z1, 1);
                float p2 = __shfl_xor_sync(0xffffffffu, z2, 1);
                float p3 = __shfl_xor_sync(0xffffffffu, z3, 1);
                if ((tg & 1) == 0) {
                    int jj = cb >> 2;
                    {
                        float si = sigmoidf(z0), sf = sigmoidf(z1);
                        float gg = tanhf(p0),    so = sigmoidf(p1);
                        float cn = sf * cst[(size_t)r * H + jj] + si * gg;
                        cst[(size_t)r * H + jj] = cn;
                        hH[(size_t)r * H + jj] = __float2half(so * tanhf(cn));
                    }
                    {
                        float si = sigmoidf(z2), sf = sigmoidf(z3);
                        float gg = tanhf(p2),    so = sigmoidf(p3);
                        float cn = sf * cst[(size_t)(r + 8) * H + jj] + si * gg;
                        cst[(size_t)(r + 8) * H + jj] = cn;
                        hH[(size_t)(r + 8) * H + jj] = __float2half(so * tanhf(cn));
                    }
                }
            }
        }
    } else if (act == 2) {
        int mbase = (col0 >> 4) + wn * 2;
        #pragma unroll
        for (int mt = 0; mt < 2; mt++) {
            int r = row0 + wm * 32 + mt * 16 + gid;
            float accA0 = 0.f, accA1 = 0.f;
            float accB0 = 0.f, accB1 = 0.f;
            #pragma unroll
            for (int nt = 0; nt < 4; nt++) {
                int n = (nt & 1) * 8 + tg * 2;
                int cbg = col0 + wn * 32 + nt * 8 + tg * 2;
                float b0 = bias0[cbg], b1 = bias0[cbg + 1];
                float d0 = dyp[r * NN + n],       d1 = dyp[r * NN + n + 1];
                float d2 = dyp[(r + 8) * NN + n], d3 = dyp[(r + 8) * NN + n + 1];
                float t0 = (c[mt][nt][0] + b0) * d0 + (c[mt][nt][1] + b1) * d1;
                float t1 = (c[mt][nt][2] + b0) * d2 + (c[mt][nt][3] + b1) * d3;
                if (nt < 2) { accA0 += t0; accA1 += t1; }
                else        { accB0 += t0; accB1 += t1; }
            }
            accA0 += __shfl_xor_sync(0xffffffffu, accA0, 1);
            accA0 += __shfl_xor_sync(0xffffffffu, accA0, 2);
            accA1 += __shfl_xor_sync(0xffffffffu, accA1, 1);
            accA1 += __shfl_xor_sync(0xffffffffu, accA1, 2);
            accB0 += __shfl_xor_sync(0xffffffffu, accB0, 1);
            accB0 += __shfl_xor_sync(0xffffffffu, accB0, 2);
            accB1 += __shfl_xor_sync(0xffffffffu, accB1, 1);
            accB1 += __shfl_xor_sync(0xffffffffu, accB1, 2);
            if (tg == 0) {
                int m0 = mbase, m1 = mbase + 1;
                outp[r * MM + m0]       = xpr[r * MM + m0]       + accA0;
                outp[(r + 8) * MM + m0] = xpr[(r + 8) * MM + m0] + accA1;
                outp[r * MM + m1]       = xpr[r * MM + m1]       + accB0;
                outp[(r + 8) * MM + m1] = xpr[(r + 8) * MM + m1] + accB1;
            }
        }
    } else {
        #pragma unroll
        for (int mt = 0; mt < 2; mt++) {
            int r = row0 + wm * 32 + mt * 16 + gid;
            #pragma unroll
            for (int nt = 0; nt < 4; nt++) {
                int cb = col0 + wn * 32 + nt * 8 + tg * 2;
                float b0a = bias0[cb], b0b = bias0[cb + 1];
                float v0 = c[mt][nt][0] + b0a;
                float v1 = c[mt][nt][1] + b0b;
                float v2 = c[mt][nt][2] + b0a;
                float v3 = c[mt][nt][3] + b0b;
                if (act) {
                    v0 = fmaxf(v0, 0.f); v1 = fmaxf(v1, 0.f);
                    v2 = fmaxf(v2, 0.f); v3 = fmaxf(v3, 0.f);
                }
                *reinterpret_cast<__half2*>(&Zh[(size_t)r * Nout + cb]) =
                    __floats2half2_rn(v0, v1);
                *reinterpret_cast<__half2*>(&Zh[(size_t)(r + 8) * Nout + cb]) =
                    __floats2half2_rn(v2, v3);
            }
        }
    }
}

// ---------------- host orchestration ----------------
extern "C" void kernel_launch(void* const* d_in, const int* in_sizes, int n_in,
                              void* d_out, int out_size)
{
    const float* Y       = (const float*)d_in[0];
    const float* x0      = (const float*)d_in[1];
    const float* Wq_ih   = (const float*)d_in[2];
    const float* Wq_hh   = (const float*)d_in[3];
    const float* bq_ih   = (const float*)d_in[4];
    const float* bq_hh   = (const float*)d_in[5];
    const float* Wsig_ih = (const float*)d_in[6];
    const float* Wsig_hh = (const float*)d_in[7];
    const float* bsig_ih = (const float*)d_in[8];
    const float* bsig_hh = (const float*)d_in[9];
    const float* Ws_ih   = (const float*)d_in[10];
    const float* Ws_hh   = (const float*)d_in[11];
    const float* bs_ih   = (const float*)d_in[12];
    const float* bs_hh   = (const float*)d_in[13];
    const float* fc1_w   = (const float*)d_in[14];
    const float* fc1_b   = (const float*)d_in[15];
    const float* fc2a_w  = (const float*)d_in[16];
    const float* fc2a_b  = (const float*)d_in[17];
    const float* fc2b_w  = (const float*)d_in[18];
    const float* fc2b_b  = (const float*)d_in[19];
    const float* fc5_w   = (const float*)d_in[20];
    const float* fc5_b   = (const float*)d_in[21];
    const float* fc6_w   = (const float*)d_in[22];
    const float* fc6_b   = (const float*)d_in[23];
    const float* fc7_w   = (const float*)d_in[24];
    const float* fc7_b   = (const float*)d_in[25];

    float* out = (float*)d_out;   // [T, B, M, 1]

    __half *WqihH, *WqhhH, *WsigihH, *WsighhH, *WsihH, *WshhH, *fc1H, *fc2aH, *fc2bH;
    __half *hQ0, *hSig0, *hS0, *out5, *out6, *out7, *out1, *a2;
    float *cQ, *cSig, *cS, *xprior0, *dy, *yprev0;
    cudaGetSymbolAddress((void**)&WqihH,   g_WqihH);
    cudaGetSymbolAddress((void**)&WqhhH,   g_WqhhH);
    cudaGetSymbolAddress((void**)&WsigihH, g_WsigihH);
    cudaGetSymbolAddress((void**)&WsighhH, g_WsighhH);
    cudaGetSymbolAddress((void**)&WsihH,   g_WsihH);
    cudaGetSymbolAddress((void**)&WshhH,   g_WshhH);
    cudaGetSymbolAddress((void**)&fc1H,    g_fc1H);
    cudaGetSymbolAddress((void**)&fc2aH,   g_fc2aH);
    cudaGetSymbolAddress((void**)&fc2bH,   g_fc2bH);
    cudaGetSymbolAddress((void**)&hQ0,     g_hQh);
    cudaGetSymbolAddress((void**)&hSig0,   g_hSigh);
    cudaGetSymbolAddress((void**)&hS0,     g_hSh);
    cudaGetSymbolAddress((void**)&out5,    g_out5h);
    cudaGetSymbolAddress((void**)&out6,    g_out6h);
    cudaGetSymbolAddress((void**)&out7,    g_out7h);
    cudaGetSymbolAddress((void**)&out1,    g_out1h);
    cudaGetSymbolAddress((void**)&a2,      g_a2h);
    cudaGetSymbolAddress((void**)&cQ,      g_cQ);
    cudaGetSymbolAddress((void**)&cSig,    g_cSig);
    cudaGetSymbolAddress((void**)&cS,      g_cS);
    cudaGetSymbolAddress((void**)&xprior0, g_xprior);
    cudaGetSymbolAddress((void**)&dy,      g_dy);
    cudaGetSymbolAddress((void**)&yprev0,  g_yprev0);

    __half* hQ[2]   = {hQ0,   hQ0   + BB * HQ};
    __half* hSig[2] = {hSig0, hSig0 + BB * HQ};
    __half* hS[2]   = {hS0,   hS0   + BB * HS};
    float* xprior_buf[2] = {xprior0, xprior0 + BB * MM};

    const GSeg nil = {nullptr, nullptr, 0, 0};

    // PDL launch config (programmatic stream serialization)
    cudaLaunchAttribute pdlAttr;
    pdlAttr.id = cudaLaunchAttributeProgrammaticStreamSerialization;
    pdlAttr.val.programmaticStreamSerializationAllowed = 1;
    cudaLaunchConfig_t cfg = {};
    cfg.attrs = &pdlAttr;
    cfg.numAttrs = 1;
    cfg.stream = 0;

    // merged weight conversion: one launch
    CvtJobs J;
    J.src[0] = Wq_ih;   J.dst[0] = WqihH;   J.K[0] = D_Q_IN;   J.H[0] = HQ;
    J.src[1] = Wq_hh;   J.dst[1] = WqhhH;   J.K[1] = HQ;       J.H[1] = HQ;
    J.src[2] = Wsig_ih; J.dst[2] = WsigihH; J.K[2] = D_SIG_IN; J.H[2] = HQ;
    J.src[3] = Wsig_hh; J.dst[3] = WsighhH; J.K[3] = HQ;       J.H[3] = HQ;
    J.src[4] = Ws_ih;   J.dst[4] = WsihH;   J.K[4] = D_S_IN;   J.H[4] = HS;
    J.src[5] = Ws_hh;   J.dst[5] = WshhH;   J.K[5] = HS;       J.H[5] = HS;
    J.src[6] = fc1_w;   J.dst[6] = fc1H;    J.K[6] = HQ;       J.H[6] = 0;
    J.src[7] = fc2a_w;  J.dst[7] = fc2aH;   J.K[7] = D_FC2_IN; J.H[7] = 0;
    J.src[8] = fc2b_w;  J.dst[8] = fc2bH;   J.K[8] = D_FC2_H;  J.H[8] = 0;
    int acc = 0;
    int rows[9] = {4 * HQ, 4 * HQ, 4 * HQ, 4 * HQ, 4 * HS, 4 * HS, HS, D_FC2_H, NN * MM};
    for (int i = 0; i < 9; i++) { J.row0[i] = acc; acc += rows[i]; }
    J.row0[9] = acc;

    cfg.gridDim = dim3(acc); cfg.blockDim = dim3(128);
    cudaLaunchKernelEx(&cfg, cvt_all, J);

    cfg.gridDim = dim3((BB * HQ + 255) / 256); cfg.blockDim = dim3(256);
    cudaLaunchKernelEx(&cfg, init_kernel, x0, (float*)yprev0);

    for (int t = 0; t < TT; t++) {
        const float* x_post      = (t == 0) ? x0 : out + (size_t)(t - 1) * BB * MM;
        const float* x_post_prev = (t <= 1) ? x0 : out + (size_t)(t - 2) * BB * MM;
        const float* x_prior_prev= (t == 0) ? x0 : xprior_buf[(t - 1) & 1];
        const float* y_t         = Y + (size_t)t * BB * NN;
        const float* y_prev      = (t == 0) ? yprev0 : Y + (size_t)(t - 1) * BB * NN;
        float* x_prior           = xprior_buf[t & 1];
        int rd = t & 1, wr = rd ^ 1;

        cfg.gridDim = dim3(BB); cfg.blockDim = dim3(192);
        cudaLaunchKernelEx(&cfg, pre_fc_kernel,
                           x_post, x_post_prev, x_prior_prev, y_t, y_prev,
                           x_prior, (float*)dy,
                           fc5_w, fc5_b, fc6_w, fc6_b, fc7_w, fc7_b,
                           out5, out6, out7);

        cfg.blockDim = dim3(128);

        // LSTM Q
        {
            GSeg a = {out5,   WqihH, D_Q_IN, D_Q_IN};
            GSeg b = {hQ[rd], WqhhH, HQ,     HQ};
            cfg.gridDim = dim3(4 * HQ / 64, BB / 64);
            cudaLaunchKernelEx(&cfg, gemm_tc, a, b, nil, 2, bq_ih, bq_hh,
                               (__half*)nullptr, 0, 0, HQ, cQ, hQ[wr],
                               (const float*)nullptr, (const float*)nullptr,
                               (float*)nullptr);
        }

        // LSTM Sigma: input = concat(hQ_new, out6)
        {
            GSeg a = {hQ[wr],   WsigihH,      HQ,     D_SIG_IN};
            GSeg b = {out6,     WsigihH + HQ, D_Q_IN, D_SIG_IN};
            GSeg c = {hSig[rd], WsighhH,      HQ,     HQ};
            cfg.gridDim = dim3(4 * HQ / 64, BB / 64);
            cudaLaunchKernelEx(&cfg, gemm_tc, a, b, c, 3, bsig_ih, bsig_hh,
                               (__half*)nullptr, 0, 0, HQ, cSig, hSig[wr],
                               (const float*)nullptr, (const float*)nullptr,
                               (float*)nullptr);
        }

        // fc1
        {
            GSeg a = {hSig[wr], fc1H, HQ, HQ};
            cfg.gridDim = dim3(HS / 64, BB / 64);
            cudaLaunchKernelEx(&cfg, gemm_tc, a, nil, nil, 1, fc1_b,
                               (const float*)nullptr,
                               out1, HS, 1, 0, (float*)nullptr, (__half*)nullptr,
                               (const float*)nullptr, (const float*)nullptr,
                               (float*)nullptr);
        }

        // LSTM S: input = concat(out1, out7)
        {
            GSeg a = {out1,   WsihH,      HS,     D_S_IN};
            GSeg b = {out7,   WsihH + HS, D_Q_IN, D_S_IN};
            GSeg c = {hS[rd], WshhH,      HS,     HS};
            cfg.gridDim = dim3(4 * HS / 64, BB / 64);
            cudaLaunchKernelEx(&cfg, gemm_tc, a, b, c, 3, bs_ih, bs_hh,
                               (__half*)nullptr, 0, 0, HS, cS, hS[wr],
                               (const float*)nullptr, (const float*)nullptr,
                               (float*)nullptr);
        }

        // fc2a
        {
            GSeg a = {hSig[wr], fc2aH,      HQ, D_FC2_IN};
            GSeg b = {hS[wr],   fc2aH + HQ, HS, D_FC2_IN};
            cfg.gridDim = dim3(D_FC2_H / 64, BB / 64);
            cudaLaunchKernelEx(&cfg, gemm_tc, a, b, nil, 2, fc2a_b,
                               (const float*)nullptr,
                               a2, D_FC2_H, 1, 0, (float*)nullptr, (__half*)nullptr,
                               (const float*)nullptr, (const float*)nullptr,
                               (float*)nullptr);
        }

        // fc2b + fused KF update
        {
            GSeg a = {a2, fc2bH, D_FC2_H, D_FC2_H};
            cfg.gridDim = dim3(NN * MM / 64, BB / 64);
            cudaLaunchKernelEx(&cfg, gemm_tc, a, nil, nil, 1, fc2b_b,
                               (const float*)nullptr,
                               (__half*)nullptr, MM, 2, 0, (float*)nullptr,
                               (__half*)nullptr,
                               (const float*)dy, (const float*)x_prior,
                               out + (size_t)t * BB * MM);
        }
    }
}

// round 15
// speedup vs baseline: 1.1489x; 1.1489x over previous
#include <cuda_runtime.h>
#include <cuda_bf16.h>
#include <cuda_fp16.h>
#include <math.h>
#include <stdint.h>

// ---------------- problem constants ----------------
#define MM   32
#define NN   16
#define BB   256
#define TT   8
#define HQ   1024
#define HS   256
#define D_Q_IN   160
#define D_SIG_IN 1184
#define D_S_IN   416
#define D_FC2_IN 1280
#define D_FC2_H  2560

// ---------------- device scratch ----------------
__device__ __half g_WqihH [4 * HQ * D_Q_IN];
__device__ __half g_WqhhH [4 * HQ * HQ];
__device__ __half g_WsigihH[4 * HQ * D_SIG_IN];
__device__ __half g_WsighhH[4 * HQ * HQ];
__device__ __half g_WsihH [4 * HS * D_S_IN];
__device__ __half g_WshhH [4 * HS * HS];
__device__ __half g_fc1H  [HS * HQ];
__device__ __half g_fc2aH [D_FC2_H * D_FC2_IN];
__device__ __half g_fc2bH [NN * MM * D_FC2_H];
__device__ __half g_hQh  [2][BB * HQ];
__device__ __half g_hSigh[2][BB * HQ];
__device__ __half g_hSh  [2][BB * HS];
__device__ __half g_out5h[BB * D_Q_IN];
__device__ __half g_out6h[BB * D_Q_IN];
__device__ __half g_out7h[BB * D_Q_IN];
__device__ __half g_out1h[BB * HS];
__device__ __half g_a2h  [BB * D_FC2_H];
__device__ float g_cQ  [BB * HQ];
__device__ float g_cSig[BB * HQ];
__device__ float g_cS  [BB * HS];
__device__ float g_xprior[2][BB * MM];
__device__ float g_dy   [BB * NN];
__device__ float g_yprev0[BB * NN];

__device__ __forceinline__ float sigmoidf(float x) { return 1.f / (1.f + expf(-x)); }

// ---------------- merged weight f32->f16 conversion (one launch) ----------------
struct CvtJobs {
    const float* src[9];
    __half* dst[9];
    int K[9];
    int H[9];       // 0 = identity row map, else gate interleave with hidden H
    int row0[10];
};

__global__ void cvt_all(CvtJobs J)
{
    int b = blockIdx.x;
    int j = 0;
    #pragma unroll
    for (int i = 1; i < 9; i++) if (b >= J.row0[i]) j = i;
    int rp = b - J.row0[j];
    int K = J.K[j], H = J.H[j];
    int ro = H ? ((rp & 3) * H + (rp >> 2)) : rp;
    const float4* s = (const float4*)(J.src[j] + (size_t)ro * K);
    __half2* d = (__half2*)(J.dst[j] + (size_t)rp * K);
    for (int k = threadIdx.x; k < (K >> 2); k += blockDim.x) {
        float4 v = s[k];
        d[2 * k]     = __floats2half2_rn(v.x, v.y);
        d[2 * k + 1] = __floats2half2_rn(v.z, v.w);
    }
}

// ---------------- init: zero states, y_prev0 = tanh(x0[:, :16]) ----------------
__global__ void init_kernel(const float* __restrict__ x0, float* __restrict__ yprev0)
{
    int idx = blockIdx.x * blockDim.x + threadIdx.x;
    __half hz = __float2half(0.f);
    if (idx < BB * HQ) {
        g_hQh[0][idx] = hz; g_hQh[1][idx] = hz; g_cQ[idx] = 0.f;
        g_hSigh[0][idx] = hz; g_hSigh[1][idx] = hz; g_cSig[idx] = 0.f;
    }
    if (idx < BB * HS) { g_hSh[0][idx] = hz; g_hSh[1][idx] = hz; g_cS[idx] = 0.f; }
    if (idx < BB * NN) {
        int b = idx / NN, n = idx % NN;
        yprev0[idx] = tanhf(x0[b * MM + n]);
    }
}

// ---------------- fused prologue + fc5/6/7 (fp16 outputs) ----------------
__global__ void pre_fc_kernel(const float* __restrict__ x_post,
                              const float* __restrict__ x_post_prev,
                              const float* __restrict__ x_prior_prev,
                              const float* __restrict__ y_t,
                              const float* __restrict__ y_prev,
                              float* __restrict__ x_prior,
                              float* __restrict__ dy_buf,
                              const float* __restrict__ w5, const float* __restrict__ b5,
                              const float* __restrict__ w6, const float* __restrict__ b6,
                              const float* __restrict__ w7, const float* __restrict__ b7,
                              __half* __restrict__ out5,
                              __half* __restrict__ out6,
                              __half* __restrict__ out7)
{
    int b = blockIdx.x;
    int tid = threadIdx.x;
    __shared__ float fwu[32], fwe[32], obs[32];

    if (tid < 32) {
        int lane = tid;
        float xp   = x_post[b * MM + lane];
        float xpp  = x_post_prev[b * MM + lane];
        float xprp = x_prior_prev[b * MM + lane];

        float xpr = xp + 0.1f * sinf(xp);
        x_prior[b * MM + lane] = xpr;

        float de = xp - xpp;
        float du = xp - xprp;
        float se = de * de, su = du * du;
        #pragma unroll
        for (int o = 16; o > 0; o >>= 1) {
            se += __shfl_xor_sync(0xffffffffu, se, o);
            su += __shfl_xor_sync(0xffffffffu, su, o);
        }
        fwe[lane] = de / fmaxf(sqrtf(se), 1e-12f);
        fwu[lane] = du / fmaxf(sqrtf(su), 1e-12f);

        float y     = (lane < NN) ? y_t[b * NN + lane]    : 0.f;
        float ypv   = (lane < NN) ? y_prev[b * NN + lane] : 0.f;
        float ypred = (lane < NN) ? tanhf(xpr)            : 0.f;
        float d1 = y - ypv;
        float d2 = y - ypred;
        if (lane < NN) dy_buf[b * NN + lane] = d2;
        float s1 = d1 * d1, s2 = d2 * d2;
        #pragma unroll
        for (int o = 16; o > 0; o >>= 1) {
            s1 += __shfl_xor_sync(0xffffffffu, s1, o);
            s2 += __shfl_xor_sync(0xffffffffu, s2, o);
        }
        if (lane < NN) {
            obs[lane]      = d1 / fmaxf(sqrtf(s1), 1e-12f);
            obs[NN + lane] = d2 / fmaxf(sqrtf(s2), 1e-12f);
        }
    }
    __syncthreads();

    for (int o = tid; o < 480; o += 192) {
        int which = o / 160, oo = o - which * 160;
        const float* W; const float* Bv; const float* xs; __half* O;
        if (which == 0)      { W = w5; Bv = b5; xs = fwu; O = out5; }
        else if (which == 1) { W = w6; Bv = b6; xs = fwe; O = out6; }
        else                 { W = w7; Bv = b7; xs = obs; O = out7; }
        float acc = Bv[oo];
        const float* wr = W + oo * 32;
        #pragma unroll
        for (int k = 0; k < 32; k++) acc += xs[k] * wr[k];
        O[b * 160 + oo] = __float2half(fmaxf(acc, 0.f));
    }
}

// ---------------- FP16-storage tensor-core multi-segment GEMM ----------------
// BM=64 BN=64 BK=32(halves), 128 threads (2x2 warps, warp 32x32),
// 4-stage cp.async pipeline with ONE __syncthreads per iteration, ldmatrix loads.
struct GSeg {
    const __half* X;   // [BB, K] fp16 contiguous
    const __half* W;   // fp16 row-major, row stride ldw (may carry column offset)
    int K;
    int ldw;
};

#define LDAH 40
#define NSTAGE 4

__device__ __forceinline__ void cpa16(void* s, const void* g) {
    uint32_t sa = (uint32_t)__cvta_generic_to_shared(s);
    asm volatile("cp.async.cg.shared.global [%0], [%1], 16;\n" :: "r"(sa), "l"(g));
}
__device__ __forceinline__ void ldm_x4(uint32_t* r, const __half* p) {
    uint32_t a = (uint32_t)__cvta_generic_to_shared(p);
    asm volatile("ldmatrix.sync.aligned.m8n8.x4.shared.b16 {%0,%1,%2,%3}, [%4];"
                 : "=r"(r[0]), "=r"(r[1]), "=r"(r[2]), "=r"(r[3]) : "r"(a));
}

__global__ void __launch_bounds__(128) gemm_tc(
    GSeg s0, GSeg s1, GSeg s2, int nseg,
    const float* __restrict__ bias0, const float* __restrict__ bias1,
    __half* __restrict__ Zh, int Nout, int act,
    int lstmH, float* __restrict__ cst, __half* __restrict__ hH,
    const float* __restrict__ dyp, const float* __restrict__ xpr,
    float* __restrict__ outp)
{
    __shared__ __half As[NSTAGE][64 * LDAH];
    __shared__ __half Bs[NSTAGE][64 * LDAH];

    int tid  = threadIdx.x;
    int lane = tid & 31;
    int wid  = tid >> 5;
    int wm   = wid & 1;
    int wn   = wid >> 1;
    int gid  = lane >> 2;
    int tg   = lane & 3;

    int row0 = blockIdx.y * 64;
    int col0 = blockIdx.x * 64;

    int srow = tid >> 2;          // 0..31
    int scol = (tid & 3) * 8;     // 0,8,16,24

    int lt   = lane >> 3;
    int lrow = lane & 7;
    int aRowOff = ((lt & 1) * 8 + lrow);
    int aKOff   = (lt >> 1) * 8;
    int bRowOff = ((lt >> 1) * 8 + lrow);
    int bKOff   = (lt & 1) * 8;

    int totK = s0.K + ((nseg > 1) ? s1.K : 0) + ((nseg > 2) ? s2.K : 0);
    int niter = totK >> 5;

    float c[2][4][4];
    #pragma unroll
    for (int mt = 0; mt < 2; mt++)
        #pragma unroll
        for (int nt = 0; nt < 4; nt++)
            #pragma unroll
            for (int r = 0; r < 4; r++) c[mt][nt][r] = 0.f;

    auto issue = [&](int it, int p) {
        int kb = it << 5;
        const __half* X = s0.X; const __half* W = s0.W; int K = s0.K; int ldw = s0.ldw;
        if (kb >= s0.K) {
            kb -= s0.K;
            if (nseg > 2 && kb >= s1.K) { kb -= s1.K; X = s2.X; W = s2.W; K = s2.K; ldw = s2.ldw; }
            else                        {             X = s1.X; W = s1.W; K = s1.K; ldw = s1.ldw; }
        }
        #pragma unroll
        for (int i = 0; i < 2; i++) {
            int r = srow + 32 * i;
            cpa16(&As[p][r * LDAH + scol], X + (size_t)(row0 + r) * K + kb + scol);
            cpa16(&Bs[p][r * LDAH + scol], W + (size_t)(col0 + r) * ldw + kb + scol);
        }
        asm volatile("cp.async.commit_group;\n" ::);
    };

    // prologue: fill stages 0..2 (empty commits keep group accounting uniform)
    #pragma unroll
    for (int i = 0; i < NSTAGE - 1; i++) {
        if (i < niter) issue(i, i);
        else asm volatile("cp.async.commit_group;\n" ::);
    }

    for (int it = 0; it < niter; it++) {
        int p = it & (NSTAGE - 1);
        asm volatile("cp.async.wait_group %0;\n" :: "n"(NSTAGE - 2));
        __syncthreads();
        if (it + NSTAGE - 1 < niter) issue(it + NSTAGE - 1, (it + NSTAGE - 1) & (NSTAGE - 1));
        else asm volatile("cp.async.commit_group;\n" ::);

        #pragma unroll
        for (int ks = 0; ks < 2; ks++) {
            int kk = ks * 16;
            uint32_t af[2][4];
            #pragma unroll
            for (int mt = 0; mt < 2; mt++) {
                int r = wm * 32 + mt * 16 + aRowOff;
                ldm_x4(af[mt], &As[p][r * LDAH + kk + aKOff]);
            }
            uint32_t bf[4][2];
            #pragma unroll
            for (int ntp = 0; ntp < 2; ntp++) {
                int n = wn * 32 + ntp * 16 + bRowOff;
                uint32_t tmp[4];
                ldm_x4(tmp, &Bs[p][n * LDAH + kk + bKOff]);
                bf[2 * ntp][0]     = tmp[0];
                bf[2 * ntp][1]     = tmp[1];
                bf[2 * ntp + 1][0] = tmp[2];
                bf[2 * ntp + 1][1] = tmp[3];
            }
            #pragma unroll
            for (int mt = 0; mt < 2; mt++)
                #pragma unroll
                for (int nt = 0; nt < 4; nt++) {
                    asm volatile(
                        "mma.sync.aligned.m16n8k16.row.col.f32.f16.f16.f32 "
                        "{%0,%1,%2,%3}, {%4,%5,%6,%7}, {%8,%9}, {%0,%1,%2,%3};\n"
                        : "+f"(c[mt][nt][0]), "+f"(c[mt][nt][1]),
                          "+f"(c[mt][nt][2]), "+f"(c[mt][nt][3])
                        : "r"(af[mt][0]), "r"(af[mt][1]), "r"(af[mt][2]), "r"(af[mt][3]),
                          "r"(bf[nt][0]), "r"(bf[nt][1]));
                }
        }
    }

    if (lstmH > 0) {
        const int H = lstmH;
        #pragma unroll
        for (int mt = 0; mt < 2; mt++) {
            int r = row0 + wm * 32 + mt * 16 + gid;
            #pragma unroll
            for (int nt = 0; nt < 4; nt++) {
                int cb = col0 + wn * 32 + nt * 8 + tg * 2;
                int ro0 = (cb & 3) * H + (cb >> 2);
                int ro1 = ((cb + 1) & 3) * H + ((cb + 1) >> 2);
                float b0a = bias0[ro0] + bias1[ro0];
                float b0b = bias0[ro1] + bias1[ro1];
                float z0 = c[mt][nt][0] + b0a;
                float z1 = c[mt][nt][1] + b0b;
                float z2 = c[mt][nt][2] + b0a;
                float z3 = c[mt][nt][3] + b0b;
                float p0 = __shfl_xor_sync(0xffffffffu, z0, 1);
                float p1 = __shfl_xor_sync(0xffffffffu, z1, 1);
                float p2 = __shfl_xor_sync(0xffffffffu, z2, 1);
                float p3 = __shfl_xor_sync(0xffffffffu, z3, 1);
                if ((tg & 1) == 0) {
                    int jj = cb >> 2;
                    {
                        float si = sigmoidf(z0), sf = sigmoidf(z1);
                        float gg = tanhf(p0),    so = sigmoidf(p1);
                        float cn = sf * cst[(size_t)r * H + jj] + si * gg;
                        cst[(size_t)r * H + jj] = cn;
                        hH[(size_t)r * H + jj] = __float2half(so * tanhf(cn));
                    }
                    {
                        float si = sigmoidf(z2), sf = sigmoidf(z3);
                        float gg = tanhf(p2),    so = sigmoidf(p3);
                        float cn = sf * cst[(size_t)(r + 8) * H + jj] + si * gg;
                        cst[(size_t)(r + 8) * H + jj] = cn;
                        hH[(size_t)(r + 8) * H + jj] = __float2half(so * tanhf(cn));
                    }
                }
            }
        }
    } else if (act == 2) {
        int mbase = (col0 >> 4) + wn * 2;
        #pragma unroll
        for (int mt = 0; mt < 2; mt++) {
            int r = row0 + wm * 32 + mt * 16 + gid;
            float accA0 = 0.f, accA1 = 0.f;
            float accB0 = 0.f, accB1 = 0.f;
            #pragma unroll
            for (int nt = 0; nt < 4; nt++) {
                int n = (nt & 1) * 8 + tg * 2;
                int cbg = col0 + wn * 32 + nt * 8 + tg * 2;
                float b0 = bias0[cbg], b1 = bias0[cbg + 1];
                float d0 = dyp[r * NN + n],       d1 = dyp[r * NN + n + 1];
                float d2 = dyp[(r + 8) * NN + n], d3 = dyp[(r + 8) * NN + n + 1];
                float t0 = (c[mt][nt][0] + b0) * d0 + (c[mt][nt][1] + b1) * d1;
                float t1 = (c[mt][nt][2] + b0) * d2 + (c[mt][nt][3] + b1) * d3;
                if (nt < 2) { accA0 += t0; accA1 += t1; }
                else        { accB0 += t0; accB1 += t1; }
            }
            accA0 += __shfl_xor_sync(0xffffffffu, accA0, 1);
            accA0 += __shfl_xor_sync(0xffffffffu, accA0, 2);
            accA1 += __shfl_xor_sync(0xffffffffu, accA1, 1);
            accA1 += __shfl_xor_sync(0xffffffffu, accA1, 2);
            accB0 += __shfl_xor_sync(0xffffffffu, accB0, 1);
            accB0 += __shfl_xor_sync(0xffffffffu, accB0, 2);
            accB1 += __shfl_xor_sync(0xffffffffu, accB1, 1);
            accB1 += __shfl_xor_sync(0xffffffffu, accB1, 2);
            if (tg == 0) {
                int m0 = mbase, m1 = mbase + 1;
                outp[r * MM + m0]       = xpr[r * MM + m0]       + accA0;
                outp[(r + 8) * MM + m0] = xpr[(r + 8) * MM + m0] + accA1;
                outp[r * MM + m1]       = xpr[r * MM + m1]       + accB0;
                outp[(r + 8) * MM + m1] = xpr[(r + 8) * MM + m1] + accB1;
            }
        }
    } else {
        #pragma unroll
        for (int mt = 0; mt < 2; mt++) {
            int r = row0 + wm * 32 + mt * 16 + gid;
            #pragma unroll
            for (int nt = 0; nt < 4; nt++) {
                int cb = col0 + wn * 32 + nt * 8 + tg * 2;
                float b0a = bias0[cb], b0b = bias0[cb + 1];
                float v0 = c[mt][nt][0] + b0a;
                float v1 = c[mt][nt][1] + b0b;
                float v2 = c[mt][nt][2] + b0a;
                float v3 = c[mt][nt][3] + b0b;
                if (act) {
                    v0 = fmaxf(v0, 0.f); v1 = fmaxf(v1, 0.f);
                    v2 = fmaxf(v2, 0.f); v3 = fmaxf(v3, 0.f);
                }
                *reinterpret_cast<__half2*>(&Zh[(size_t)r * Nout + cb]) =
                    __floats2half2_rn(v0, v1);
                *reinterpret_cast<__half2*>(&Zh[(size_t)(r + 8) * Nout + cb]) =
                    __floats2half2_rn(v2, v3);
            }
        }
    }
}

// ---------------- host orchestration ----------------
extern "C" void kernel_launch(void* const* d_in, const int* in_sizes, int n_in,
                              void* d_out, int out_size)
{
    const float* Y       = (const float*)d_in[0];
    const float* x0      = (const float*)d_in[1];
    const float* Wq_ih   = (const float*)d_in[2];
    const float* Wq_hh   = (const float*)d_in[3];
    const float* bq_ih   = (const float*)d_in[4];
    const float* bq_hh   = (const float*)d_in[5];
    const float* Wsig_ih = (const float*)d_in[6];
    const float* Wsig_hh = (const float*)d_in[7];
    const float* bsig_ih = (const float*)d_in[8];
    const float* bsig_hh = (const float*)d_in[9];
    const float* Ws_ih   = (const float*)d_in[10];
    const float* Ws_hh   = (const float*)d_in[11];
    const float* bs_ih   = (const float*)d_in[12];
    const float* bs_hh   = (const float*)d_in[13];
    const float* fc1_w   = (const float*)d_in[14];
    const float* fc1_b   = (const float*)d_in[15];
    const float* fc2a_w  = (const float*)d_in[16];
    const float* fc2a_b  = (const float*)d_in[17];
    const float* fc2b_w  = (const float*)d_in[18];
    const float* fc2b_b  = (const float*)d_in[19];
    const float* fc5_w   = (const float*)d_in[20];
    const float* fc5_b   = (const float*)d_in[21];
    const float* fc6_w   = (const float*)d_in[22];
    const float* fc6_b   = (const float*)d_in[23];
    const float* fc7_w   = (const float*)d_in[24];
    const float* fc7_b   = (const float*)d_in[25];

    float* out = (float*)d_out;   // [T, B, M, 1]

    __half *WqihH, *WqhhH, *WsigihH, *WsighhH, *WsihH, *WshhH, *fc1H, *fc2aH, *fc2bH;
    __half *hQ0, *hSig0, *hS0, *out5, *out6, *out7, *out1, *a2;
    float *cQ, *cSig, *cS, *xprior0, *dy, *yprev0;
    cudaGetSymbolAddress((void**)&WqihH,   g_WqihH);
    cudaGetSymbolAddress((void**)&WqhhH,   g_WqhhH);
    cudaGetSymbolAddress((void**)&WsigihH, g_WsigihH);
    cudaGetSymbolAddress((void**)&WsighhH, g_WsighhH);
    cudaGetSymbolAddress((void**)&WsihH,   g_WsihH);
    cudaGetSymbolAddress((void**)&WshhH,   g_WshhH);
    cudaGetSymbolAddress((void**)&fc1H,    g_fc1H);
    cudaGetSymbolAddress((void**)&fc2aH,   g_fc2aH);
    cudaGetSymbolAddress((void**)&fc2bH,   g_fc2bH);
    cudaGetSymbolAddress((void**)&hQ0,     g_hQh);
    cudaGetSymbolAddress((void**)&hSig0,   g_hSigh);
    cudaGetSymbolAddress((void**)&hS0,     g_hSh);
    cudaGetSymbolAddress((void**)&out5,    g_out5h);
    cudaGetSymbolAddress((void**)&out6,    g_out6h);
    cudaGetSymbolAddress((void**)&out7,    g_out7h);
    cudaGetSymbolAddress((void**)&out1,    g_out1h);
    cudaGetSymbolAddress((void**)&a2,      g_a2h);
    cudaGetSymbolAddress((void**)&cQ,      g_cQ);
    cudaGetSymbolAddress((void**)&cSig,    g_cSig);
    cudaGetSymbolAddress((void**)&cS,      g_cS);
    cudaGetSymbolAddress((void**)&xprior0, g_xprior);
    cudaGetSymbolAddress((void**)&dy,      g_dy);
    cudaGetSymbolAddress((void**)&yprev0,  g_yprev0);

    __half* hQ[2]   = {hQ0,   hQ0   + BB * HQ};
    __half* hSig[2] = {hSig0, hSig0 + BB * HQ};
    __half* hS[2]   = {hS0,   hS0   + BB * HS};
    float* xprior_buf[2] = {xprior0, xprior0 + BB * MM};

    const GSeg nil = {nullptr, nullptr, 0, 0};

    // merged weight conversion: one launch
    CvtJobs J;
    J.src[0] = Wq_ih;   J.dst[0] = WqihH;   J.K[0] = D_Q_IN;   J.H[0] = HQ;
    J.src[1] = Wq_hh;   J.dst[1] = WqhhH;   J.K[1] = HQ;       J.H[1] = HQ;
    J.src[2] = Wsig_ih; J.dst[2] = WsigihH; J.K[2] = D_SIG_IN; J.H[2] = HQ;
    J.src[3] = Wsig_hh; J.dst[3] = WsighhH; J.K[3] = HQ;       J.H[3] = HQ;
    J.src[4] = Ws_ih;   J.dst[4] = WsihH;   J.K[4] = D_S_IN;   J.H[4] = HS;
    J.src[5] = Ws_hh;   J.dst[5] = WshhH;   J.K[5] = HS;       J.H[5] = HS;
    J.src[6] = fc1_w;   J.dst[6] = fc1H;    J.K[6] = HQ;       J.H[6] = 0;
    J.src[7] = fc2a_w;  J.dst[7] = fc2aH;   J.K[7] = D_FC2_IN; J.H[7] = 0;
    J.src[8] = fc2b_w;  J.dst[8] = fc2bH;   J.K[8] = D_FC2_H;  J.H[8] = 0;
    int acc = 0;
    int rows[9] = {4 * HQ, 4 * HQ, 4 * HQ, 4 * HQ, 4 * HS, 4 * HS, HS, D_FC2_H, NN * MM};
    for (int i = 0; i < 9; i++) { J.row0[i] = acc; acc += rows[i]; }
    J.row0[9] = acc;

    cvt_all<<<acc, 128>>>(J);

    init_kernel<<<(BB * HQ + 255) / 256, 256>>>(x0, yprev0);

    for (int t = 0; t < TT; t++) {
        const float* x_post      = (t == 0) ? x0 : out + (size_t)(t - 1) * BB * MM;
        const float* x_post_prev = (t <= 1) ? x0 : out + (size_t)(t - 2) * BB * MM;
        const float* x_prior_prev= (t == 0) ? x0 : xprior_buf[(t - 1) & 1];
        const float* y_t         = Y + (size_t)t * BB * NN;
        const float* y_prev      = (t == 0) ? yprev0 : Y + (size_t)(t - 1) * BB * NN;
        float* x_prior           = xprior_buf[t & 1];
        int rd = t & 1, wr = rd ^ 1;

        pre_fc_kernel<<<BB, 192>>>(x_post, x_post_prev, x_prior_prev, y_t, y_prev,
                                   x_prior, dy,
                                   fc5_w, fc5_b, fc6_w, fc6_b, fc7_w, fc7_b,
                                   out5, out6, out7);

        // LSTM Q
        {
            GSeg a = {out5,   WqihH, D_Q_IN, D_Q_IN};
            GSeg b = {hQ[rd], WqhhH, HQ,     HQ};
            gemm_tc<<<dim3(4 * HQ / 64, BB / 64), 128>>>(a, b, nil, 2, bq_ih, bq_hh,
                nullptr, 0, 0, HQ, cQ, hQ[wr], nullptr, nullptr, nullptr);
        }

        // LSTM Sigma: input = concat(hQ_new, out6)
        {
            GSeg a = {hQ[wr],   WsigihH,      HQ,     D_SIG_IN};
            GSeg b = {out6,     WsigihH + HQ, D_Q_IN, D_SIG_IN};
            GSeg c = {hSig[rd], WsighhH,      HQ,     HQ};
            gemm_tc<<<dim3(4 * HQ / 64, BB / 64), 128>>>(a, b, c, 3, bsig_ih, bsig_hh,
                nullptr, 0, 0, HQ, cSig, hSig[wr], nullptr, nullptr, nullptr);
        }

        // fc1
        {
            GSeg a = {hSig[wr], fc1H, HQ, HQ};
            gemm_tc<<<dim3(HS / 64, BB / 64), 128>>>(a, nil, nil, 1, fc1_b, nullptr,
                out1, HS, 1, 0, nullptr, nullptr, nullptr, nullptr, nullptr);
        }

        // LSTM S: input = concat(out1, out7)
        {
            GSeg a = {out1,   WsihH,      HS,     D_S_IN};
            GSeg b = {out7,   WsihH + HS, D_Q_IN, D_S_IN};
            GSeg c = {hS[rd], WshhH,      HS,     HS};
            gemm_tc<<<dim3(4 * HS / 64, BB / 64), 128>>>(a, b, c, 3, bs_ih, bs_hh,
                nullptr, 0, 0, HS, cS, hS[wr], nullptr, nullptr, nullptr);
        }

        // fc2a
        {
            GSeg a = {hSig[wr], fc2aH,      HQ, D_FC2_IN};
            GSeg b = {hS[wr],   fc2aH + HQ, HS, D_FC2_IN};
            gemm_tc<<<dim3(D_FC2_H / 64, BB / 64), 128>>>(a, b, nil, 2, fc2a_b, nullptr,
                a2, D_FC2_H, 1, 0, nullptr, nullptr, nullptr, nullptr, nullptr);
        }

        // fc2b + fused KF update
        {
            GSeg a = {a2, fc2bH, D_FC2_H, D_FC2_H};
            gemm_tc<<<dim3(NN * MM / 64, BB / 64), 128>>>(a, nil, nil, 1, fc2b_b, nullptr,
                nullptr, MM, 2, 0, nullptr, nullptr, dy, x_prior,
                out + (size_t)t * BB * MM);
        }
    }
}